// round 14
// baseline (speedup 1.0000x reference)
#include <cuda_runtime.h>
#include <math.h>
#include <stdint.h>

#define BB  4
#define TT  1024
#define EE  512
#define HH  8
#define EHD (EE*HH)   // 4096
#define BT  (BB*TT)   // 4096

// Scratch (device globals: allocation-free rule)
__device__ float g_WU [(size_t)EE*EHD];         // tf32-rounded w_u
__device__ float g_QK [(size_t)2*BT*EHD];       // tf32-rounded Q | K
__device__ float g_VT [(size_t)BT*EHD];         // tf32-rounded V^T per (b,h): [E][T]
__device__ float g_S  [(size_t)BB*HH*TT*TT];    // E = exp(scores), tf32-rounded
__device__ float g_A  [(size_t)BT*EHD];         // tf32-rounded attn out
__device__ float g_RS [(size_t)BB*HH*TT];       // softmax row sums

// ---------------- helpers ---------------------------------------------------
__device__ __forceinline__ void cp16(uint32_t dst, const void* src) {
    asm volatile("cp.async.cg.shared.global [%0], [%1], 16;"
                 :: "r"(dst), "l"(src) : "memory");
}
__device__ __forceinline__ uint32_t smem_u32(const void* p) {
    uint32_t a;
    asm("{ .reg .u64 t; cvta.to.shared.u64 t, %1; cvt.u32.u64 %0, t; }"
        : "=r"(a) : "l"(p));
    return a;
}
__device__ __forceinline__ uint32_t tf32b(float f) {
    uint32_t r;
    asm("cvt.rna.tf32.f32 %0, %1;" : "=r"(r) : "f"(f));
    return r;
}
__device__ __forceinline__ float tf32r(float f) {
    return __uint_as_float(tf32b(f));
}
__device__ __forceinline__ void mma_tf32(float* c, const uint32_t* a,
                                         const uint32_t* b) {
    asm volatile(
        "mma.sync.aligned.m16n8k8.row.col.f32.tf32.tf32.f32 "
        "{%0,%1,%2,%3}, {%4,%5,%6,%7}, {%8,%9}, {%0,%1,%2,%3};"
        : "+f"(c[0]), "+f"(c[1]), "+f"(c[2]), "+f"(c[3])
        : "r"(a[0]), "r"(a[1]), "r"(a[2]), "r"(a[3]),
          "r"(b[0]), "r"(b[1]));
}

// SMEM geometry: 128 rows x 32 k-words, row stride 40 words (conflict-free LDS.64)
#define T_LD      40
#define T_WORDS   (128*T_LD)          // 5120 words per operand tile
#define STAGE_W   (2*T_WORDS)         // 10240 words = 40KB
#define SMSZ      (2*STAGE_W*4)       // 81920 B (also covers 128x132 transpose)

// ---------------------------------------------------------------------------
// TF32 HMMA GEMM (all-NT): C = A[M,K] @ B[N,K]^T, 128x128 tile, BK=32,
// 8 warps (4x2), 32x64 per warp. Fragment loads use the logical-k remap
// (lt -> col 2lt, lt+4 -> col 2lt+1) so each (k,k+4) pair is one LDS.64.
// CVT=1: round fragments to tf32 in-loop (raw fp32 operands).
// fuse (QKV): B from {Bm,B1,B2} by zi; zi<2 -> scaled rounded store to
//             C+zi*sCi; zi==2 -> SMEM-staged transposed store into CT (V^T).
// causal: skip bn>bm tiles. kclip: Keff=min(K,bm+128).
// epi: 0 rnd(scale*acc) store; 1 exp+mask+rowsum; 2 /rsum rnd store; 3 atomicAdd.
// ---------------------------------------------------------------------------
template<int CVT>
__global__ __launch_bounds__(256) void gemm_nt(
    int K,
    const float* __restrict__ A, int lda, size_t sAo, size_t sAi,
    const float* __restrict__ Bm, int ldb, size_t sBo, size_t sBi,
    const float* __restrict__ B1, const float* __restrict__ B2,
    float* __restrict__ C, int ldc, size_t sCo, size_t sCi,
    float* __restrict__ CT,
    int fuse, float scale, int causal, int kclip, int epi,
    float* __restrict__ rsum)
{
    const int bm = blockIdx.y * 128, bn = blockIdx.x * 128;
    if (causal && bn > bm) return;

    const size_t zo = blockIdx.z >> 3, zi = blockIdx.z & 7;
    if (fuse) {
        Bm = (zi == 0) ? Bm : (zi == 1) ? B1 : B2;
        C += zi * sCi;
    } else {
        A  += zo * sAo + zi * sAi;
        Bm += zo * sBo + zi * sBi;
        C  += zo * sCo + zi * sCi;
    }
    if (rsum) rsum += (size_t)blockIdx.z * TT;

    extern __shared__ float sm[];
    const uint32_t sbase = smem_u32(sm);

    const int tid  = threadIdx.x;
    const int wid  = tid >> 5, lane = tid & 31;
    const int wm   = wid >> 1, wn = wid & 1;
    const int arow = wm * 32;
    const int bcol = wn * 64;
    const int lg   = lane >> 2, lt = lane & 3;

    const int Keff = kclip ? min(K, bm + 128) : K;
    const int nch  = Keff >> 5;

    float acc[2][8][4];
#pragma unroll
    for (int mt = 0; mt < 2; mt++)
#pragma unroll
        for (int nt = 0; nt < 8; nt++)
#pragma unroll
            for (int i = 0; i < 4; i++) acc[mt][nt][i] = 0.f;

    auto prefetch = [&](int c) {
        const int k0  = c << 5;
        const uint32_t sA = sbase + (uint32_t)((c & 1) * STAGE_W) * 4;
        const uint32_t sB = sA + T_WORDS * 4;
#pragma unroll
        for (int i = 0; i < 4; i++) {
            const int e = tid + i * 256;
            const int r = e >> 3, cw = (e & 7) * 4;
            cp16(sA + (r * T_LD + cw) * 4,
                 A + (size_t)(bm + r) * lda + k0 + cw);
            cp16(sB + (r * T_LD + cw) * 4,
                 Bm + (size_t)(bn + r) * ldb + k0 + cw);
        }
        asm volatile("cp.async.commit_group;" ::: "memory");
    };

    prefetch(0);

    for (int c = 0; c < nch; c++) {
        asm volatile("cp.async.wait_group 0;" ::: "memory");
        __syncthreads();
        if (c + 1 < nch) prefetch(c + 1);

        const float2* A2 = (const float2*)(sm + (c & 1) * STAGE_W);
        const float2* B2 = A2 + T_WORDS / 2;   // float2 units

#pragma unroll
        for (int ks = 0; ks < 4; ks++) {
            // logical-k remap: thread lt covers SMEM cols (8ks+2lt, 8ks+2lt+1)
            const int kc = 4 * ks + lt;        // float2 column index
            uint32_t a[2][4], b[8][2];
#pragma unroll
            for (int mt = 0; mt < 2; mt++) {
                const int m = arow + mt * 16 + lg;
                float2 v0 = A2[m * (T_LD / 2) + kc];
                float2 v1 = A2[(m + 8) * (T_LD / 2) + kc];
                if (CVT) {
                    a[mt][0] = tf32b(v0.x); a[mt][2] = tf32b(v0.y);
                    a[mt][1] = tf32b(v1.x); a[mt][3] = tf32b(v1.y);
                } else {
                    a[mt][0] = __float_as_uint(v0.x);
                    a[mt][2] = __float_as_uint(v0.y);
                    a[mt][1] = __float_as_uint(v1.x);
                    a[mt][3] = __float_as_uint(v1.y);
                }
            }
#pragma unroll
            for (int nt = 0; nt < 8; nt++) {
                const int n = bcol + nt * 8 + lg;
                float2 v = B2[n * (T_LD / 2) + kc];
                if (CVT) {
                    b[nt][0] = tf32b(v.x); b[nt][1] = tf32b(v.y);
                } else {
                    b[nt][0] = __float_as_uint(v.x);
                    b[nt][1] = __float_as_uint(v.y);
                }
            }
#pragma unroll
            for (int mt = 0; mt < 2; mt++)
#pragma unroll
                for (int nt = 0; nt < 8; nt++)
                    mma_tf32(acc[mt][nt], a[mt], b[nt]);
        }
    }

    // ---- epilogues ----
    if (fuse && zi == 2) {
        // V^T: stage transposed tile in SMEM, write coalesced rows of [E][T]
        __syncthreads();
        float* tsm = sm;   // [128][132]
#pragma unroll
        for (int mt = 0; mt < 2; mt++) {
            const int ml = arow + mt * 16 + lg;
#pragma unroll
            for (int nt = 0; nt < 8; nt++) {
                const int nl = bcol + nt * 8 + 2 * lt;
                tsm[nl * 132 + ml]           = acc[mt][nt][0];
                tsm[(nl + 1) * 132 + ml]     = acc[mt][nt][1];
                tsm[nl * 132 + ml + 8]       = acc[mt][nt][2];
                tsm[(nl + 1) * 132 + ml + 8] = acc[mt][nt][3];
            }
        }
        __syncthreads();
        const int bb = bm >> 10, hh = bn >> 9;
        float* base = CT + ((size_t)(bb * HH + hh) * EE + (bn & (EE - 1))) * TT
                         + (bm & (TT - 1));
#pragma unroll
        for (int i = 0; i < 16; i++) {
            const int e = tid + i * 256;        // 4096 float4 slots
            const int row = e >> 5, c4 = (e & 31) * 4;
            float4 v = *(float4*)&tsm[row * 132 + c4];
            v.x = tf32r(v.x); v.y = tf32r(v.y);
            v.z = tf32r(v.z); v.w = tf32r(v.w);
            *(float4*)&base[(size_t)row * TT + c4] = v;
        }
        return;
    }

    if (epi == 1) {
        float rs[2][2] = {{0.f, 0.f}, {0.f, 0.f}};
#pragma unroll
        for (int mt = 0; mt < 2; mt++) {
            const int r0 = bm + arow + mt * 16 + lg;
#pragma unroll
            for (int nt = 0; nt < 8; nt++) {
                const int gn = bn + bcol + nt * 8 + 2 * lt;
                float e0 = (gn     <= r0)     ? __expf(acc[mt][nt][0]) : 0.f;
                float e1 = (gn + 1 <= r0)     ? __expf(acc[mt][nt][1]) : 0.f;
                float e2 = (gn     <= r0 + 8) ? __expf(acc[mt][nt][2]) : 0.f;
                float e3 = (gn + 1 <= r0 + 8) ? __expf(acc[mt][nt][3]) : 0.f;
                rs[mt][0] += e0 + e1;
                rs[mt][1] += e2 + e3;
                float2 v0, v1;
                v0.x = tf32r(e0); v0.y = tf32r(e1);
                v1.x = tf32r(e2); v1.y = tf32r(e3);
                *(float2*)&C[(size_t)r0 * ldc + gn]       = v0;
                *(float2*)&C[(size_t)(r0 + 8) * ldc + gn] = v1;
            }
        }
#pragma unroll
        for (int mt = 0; mt < 2; mt++)
#pragma unroll
            for (int h = 0; h < 2; h++) {
                float v = rs[mt][h];
                v += __shfl_xor_sync(0xffffffffu, v, 1);
                v += __shfl_xor_sync(0xffffffffu, v, 2);
                if (lt == 0)
                    atomicAdd(&rsum[bm + arow + mt * 16 + lg + h * 8], v);
            }
    } else if (epi == 2) {
#pragma unroll
        for (int mt = 0; mt < 2; mt++) {
            const int r0 = bm + arow + mt * 16 + lg;
            const float i0 = 1.f / rsum[r0];
            const float i1 = 1.f / rsum[r0 + 8];
#pragma unroll
            for (int nt = 0; nt < 8; nt++) {
                const int gn = bn + bcol + nt * 8 + 2 * lt;
                float2 v0, v1;
                v0.x = tf32r(acc[mt][nt][0] * i0);
                v0.y = tf32r(acc[mt][nt][1] * i0);
                v1.x = tf32r(acc[mt][nt][2] * i1);
                v1.y = tf32r(acc[mt][nt][3] * i1);
                *(float2*)&C[(size_t)r0 * ldc + gn]       = v0;
                *(float2*)&C[(size_t)(r0 + 8) * ldc + gn] = v1;
            }
        }
    } else if (epi == 3) {
#pragma unroll
        for (int mt = 0; mt < 2; mt++) {
#pragma unroll
            for (int nt = 0; nt < 8; nt++) {
                const int gn = bn + bcol + nt * 8 + 2 * lt;
                const int r0 = bm + arow + mt * 16 + lg;
                atomicAdd(&C[(size_t)r0 * ldc + gn],       acc[mt][nt][0]);
                atomicAdd(&C[(size_t)r0 * ldc + gn + 1],   acc[mt][nt][1]);
                atomicAdd(&C[(size_t)(r0+8) * ldc + gn],   acc[mt][nt][2]);
                atomicAdd(&C[(size_t)(r0+8) * ldc + gn+1], acc[mt][nt][3]);
            }
        }
    } else {
        const float sc = (fuse && zi == 2) ? 1.f : scale;
#pragma unroll
        for (int mt = 0; mt < 2; mt++) {
#pragma unroll
            for (int nt = 0; nt < 8; nt++) {
                const int gn = bn + bcol + nt * 8 + 2 * lt;
                const int r0 = bm + arow + mt * 16 + lg;
                float2 v0, v1;
                v0.x = tf32r(acc[mt][nt][0] * sc);
                v0.y = tf32r(acc[mt][nt][1] * sc);
                v1.x = tf32r(acc[mt][nt][2] * sc);
                v1.y = tf32r(acc[mt][nt][3] * sc);
                *(float2*)&C[(size_t)r0 * ldc + gn]       = v0;
                *(float2*)&C[(size_t)(r0 + 8) * ldc + gn] = v1;
            }
        }
    }
}

// ---------------- pre-round fp32 -> tf32 ------------------------------------
__global__ __launch_bounds__(256) void round_tf32(
    const float4* __restrict__ src, float4* __restrict__ dst, int n4)
{
    const int i = blockIdx.x * 256 + threadIdx.x;
    if (i >= n4) return;
    float4 v = src[i];
    v.x = tf32r(v.x); v.y = tf32r(v.y);
    v.z = tf32r(v.z); v.w = tf32r(v.w);
    dst[i] = v;
}

// ---------------- out = broadcast bias; zero row sums -----------------------
__global__ __launch_bounds__(256) void init_out(
    float* __restrict__ out, const float* __restrict__ bias,
    float* __restrict__ rsum)
{
    const int i = blockIdx.x * 256 + threadIdx.x;
    out[i] = bias[i & (EE - 1)];
    if (i < BB * HH * TT) rsum[i] = 0.f;
}

// ---------------------------------------------------------------------------
extern "C" void kernel_launch(void* const* d_in, const int* in_sizes, int n_in,
                              void* d_out, int out_size)
{
    const float* x   = (const float*)d_in[0];
    const float* w_k = (const float*)d_in[1];
    const float* w_q = (const float*)d_in[2];
    const float* w_v = (const float*)d_in[3];
    const float* w_u = (const float*)d_in[4];
    const float* b_u = (const float*)d_in[5];
    float* out = (float*)d_out;

    void *pWU, *pQK, *pVT, *pS, *pA, *pRS;
    cudaGetSymbolAddress(&pWU, g_WU);
    cudaGetSymbolAddress(&pQK, g_QK);
    cudaGetSymbolAddress(&pVT, g_VT);
    cudaGetSymbolAddress(&pS,  g_S);
    cudaGetSymbolAddress(&pA,  g_A);
    cudaGetSymbolAddress(&pRS, g_RS);
    float* WU = (float*)pWU;
    float* QK = (float*)pQK;
    float* VT = (float*)pVT;
    float* Sc = (float*)pS;
    float* Ab = (float*)pA;
    float* RS = (float*)pRS;

    float* Qp = QK;
    float* Kp = QK + (size_t)BT * EHD;

    static int init = 0;
    if (!init) {
        cudaFuncSetAttribute(gemm_nt<1>,
            cudaFuncAttributeMaxDynamicSharedMemorySize, SMSZ);
        cudaFuncSetAttribute(gemm_nt<0>,
            cudaFuncAttributeMaxDynamicSharedMemorySize, SMSZ);
        init = 1;
    }

    const float s = 0.21022410381342864f;  // 512^(-1/4), applied to Q,K planes
    const dim3 blk(256);
    const size_t z = 0;

    // 0) round w_u; bias-init out (split-K target); zero row sums
    const int n4 = (EE * EHD) / 4;
    round_tf32<<<(n4 + 255) / 256, 256>>>((const float4*)w_u, (float4*)WU, n4);
    init_out<<<(BT * EE) / 256, 256>>>(out, b_u, RS);

    // 1) fused QKV (zi: 0=Q scaled, 1=K scaled, 2=V transposed into VT)
    gemm_nt<1><<<dim3(32, 32, 3), blk, SMSZ>>>(EE,
        x,   EE, z, z,
        w_q, EE, z, z,  w_k, w_v,
        QK, EHD, z, (size_t)BT * EHD,  VT,
        1, s, 0, 0, 0, nullptr);

    // 2) scores + fused exp/mask/row-sum: E = exp(Q @ K^T), causal tile skip
    gemm_nt<0><<<dim3(8, 8, 32), blk, SMSZ>>>(EE,
        Qp, EHD, (size_t)TT*EHD, (size_t)EE,
        Kp, EHD, (size_t)TT*EHD, (size_t)EE,  nullptr, nullptr,
        Sc, TT,  (size_t)HH*TT*TT, (size_t)TT*TT,  nullptr,
        0, 1.f, 1, 0, 1, RS);

    // 3) PV (now NT): O = (E @ VT^T) / rsum, K clipped by causality
    gemm_nt<0><<<dim3(4, 8, 32), blk, SMSZ>>>(TT,
        Sc, TT, (size_t)HH*TT*TT, (size_t)TT*TT,
        VT, TT, (size_t)HH*EE*TT, (size_t)EE*TT,  nullptr, nullptr,
        Ab, EHD, (size_t)TT*EHD, (size_t)EE,  nullptr,
        0, 1.f, 0, 1, 2, RS);

    // 4) unify: out += Ab @ WU^T, split-K=2 via zi, atomic epilogue
    gemm_nt<0><<<dim3(4, 32, 2), blk, SMSZ>>>(EHD / 2,
        Ab, EHD, z, (size_t)(EHD / 2),
        WU, EHD, z, (size_t)(EHD / 2),  nullptr, nullptr,
        out, EE, z, z,  nullptr,
        0, 1.f, 0, 0, 3, nullptr);
}